// round 10
// baseline (speedup 1.0000x reference)
#include <cuda_runtime.h>
#include <cuda_fp16.h>

#define DFEAT 64
#define MAXN 50048
#define MAXE 1600000
#define CAP 128   // bucket capacity; in-deg Poisson(32), 128 ~ 17 sigma

// ---------------- scratch (device globals; zero-initialized) ----------------
__device__ int     g_cnt[MAXN];            // in-degree counters (re-zeroed by kernel C)
__device__ int     g_col2[MAXN * CAP];     // bucketed adjacency
__device__ __half2 g_s[MAXN * 32];         // s1 = x@W1 (unscaled, fp16)
__device__ __half2 g_s2[MAXN * 32];        // s2 = dinv ⊙ (h@W2) (fp16)

// ---------------- shared gemm mainloop (FFMA2), operands in smem ------------
template<int SCALE>
__device__ __forceinline__ void gemm_tile_from_smem(
    const float* Ws, const float* Xt, int row0, int n, int tid, __half2* outbuf)
{
    int tx = tid & 15;      // cols tx*4 .. tx*4+3
    int ty = tid >> 4;      // rows ty*4 .. ty*4+3
    unsigned long long accA[4] = {0ull, 0ull, 0ull, 0ull};
    unsigned long long accB[4] = {0ull, 0ull, 0ull, 0ull};

#pragma unroll 8
    for (int k = 0; k < DFEAT; k++) {
        float4 xv = *(const float4*)&Xt[k * 68 + ty * 4];
        ulonglong2 wv = *(const ulonglong2*)&Ws[k * 68 + tx * 4];
        float xr[4] = {xv.x, xv.y, xv.z, xv.w};
#pragma unroll
        for (int r = 0; r < 4; r++) {
            unsigned int xu = __float_as_uint(xr[r]);
            unsigned long long ax;
            asm("mov.b64 %0, {%1,%1};" : "=l"(ax) : "r"(xu));
            asm("fma.rn.f32x2 %0, %1, %2, %0;" : "+l"(accA[r]) : "l"(ax), "l"(wv.x));
            asm("fma.rn.f32x2 %0, %1, %2, %0;" : "+l"(accB[r]) : "l"(ax), "l"(wv.y));
        }
    }

#pragma unroll
    for (int r = 0; r < 4; r++) {
        int gr = row0 + ty * 4 + r;
        if (gr < n) {
            unsigned int u0, u1, u2, u3;
            asm("mov.b64 {%0,%1}, %2;" : "=r"(u0), "=r"(u1) : "l"(accA[r]));
            asm("mov.b64 {%0,%1}, %2;" : "=r"(u2), "=r"(u3) : "l"(accB[r]));
            float o0 = __uint_as_float(u0), o1 = __uint_as_float(u1);
            float o2 = __uint_as_float(u2), o3 = __uint_as_float(u3);
            if (SCALE) {
                float di = rsqrtf((float)(g_cnt[gr] + 1));
                o0 *= di; o1 *= di; o2 *= di; o3 *= di;
            }
            __half2 h0 = __floats2half2_rn(o0, o1);
            __half2 h1 = __floats2half2_rn(o2, o3);
            uint2 pk;
            pk.x = *(unsigned int*)&h0;
            pk.y = *(unsigned int*)&h1;
            *(uint2*)&outbuf[gr * 32 + tx * 2] = pk;
        }
    }
}

// ---------------- Kernel A: fat kernel = gemm1  ∪  edge-bucket fill ---------
__global__ __launch_bounds__(256) void build_gemm1_kernel(
    const float* __restrict__ x, const float* __restrict__ W1,
    const int* __restrict__ ei, int n, int E, int gemm_blocks)
{
    __shared__ float Ws[DFEAT * 68];
    __shared__ float Xt[DFEAT * 68];

    int tid = threadIdx.x;
    if ((int)blockIdx.x < gemm_blocks) {
        // ---- gemm1: s1 = x @ W1 (unscaled) ----
        const float4* __restrict__ W4 = (const float4*)W1;
        const float4* __restrict__ X4 = (const float4*)x;
        int row0 = blockIdx.x * 64;
        for (int i = tid; i < 64 * 16; i += 256) {
            int r = i >> 4, c4 = i & 15;
            *(float4*)&Ws[r * 68 + c4 * 4] = W4[i];
            int gr = row0 + r;
            float4 xv = (gr < n) ? X4[gr * 16 + c4] : make_float4(0.f, 0.f, 0.f, 0.f);
            int k0 = c4 * 4;
            Xt[(k0 + 0) * 68 + r] = xv.x;
            Xt[(k0 + 1) * 68 + r] = xv.y;
            Xt[(k0 + 2) * 68 + r] = xv.z;
            Xt[(k0 + 3) * 68 + r] = xv.w;
        }
        __syncthreads();
        gemm_tile_from_smem<0>(Ws, Xt, row0, n, tid, g_s);
    } else {
        // ---- edge fill: 8 edges per thread ----
        int base = (blockIdx.x - gemm_blocks) * 2048 + tid;
#pragma unroll
        for (int q = 0; q < 8; q++) {
            int e = base + q * 256;
            if (e < E) {
                int src = ei[e];
                int dst = ei[E + e];
                if ((unsigned)dst < (unsigned)n && (unsigned)src < (unsigned)n) {
                    int pos = atomicAdd(&g_cnt[dst], 1);
                    if (pos < CAP) g_col2[dst * CAP + pos] = src;
                }
            }
        }
    }
}

// ---------------- Kernel B: fused agg1 (64 nodes) + gemm2 -------------------
// phase 1: h_r = relu(dinv_i*(dinv_i*s1_i + sum dinv_s*s1_s) + b1) -> smem Xt
// phase 2: s2 = dinv ⊙ (h @ W2) -> g_s2 (fp16)
__global__ __launch_bounds__(256) void agg1_gemm2_kernel(
    const float* __restrict__ b1, const float* __restrict__ W2, int n)
{
    __shared__ float Ws[DFEAT * 68];
    __shared__ float Xt[DFEAT * 68];   // holds h transposed: Xt[k][r]

    int tid = threadIdx.x;
    int row0 = blockIdx.x * 64;

    // load W2 tile
    const float4* __restrict__ W4 = (const float4*)W2;
    for (int i = tid; i < 64 * 16; i += 256) {
        int r = i >> 4, c4 = i & 15;
        *(float4*)&Ws[r * 68 + c4 * 4] = W4[i];
    }

    // phase 1: each warp aggregates 8 nodes
    int w = tid >> 5, lane = tid & 31;
    float2 b = ((const float2*)b1)[lane];
#pragma unroll 1
    for (int j = 0; j < 8; j++) {
        int i = row0 + w * 8 + j;
        if (i < n) {
            int cnt = g_cnt[i];
            int deg = min(cnt, CAP);
            float di = rsqrtf((float)(cnt + 1));
            float2 self = __half22float2(g_s[i * 32 + lane]);
            float2 acc = make_float2(di * self.x, di * self.y);

            const int* __restrict__ row = &g_col2[i * CAP];
            int e = 0;
            for (; e + 4 <= deg; e += 4) {
                int s0 = row[e], s1 = row[e + 1], s2 = row[e + 2], s3 = row[e + 3];
                float2 v0 = __half22float2(g_s[s0 * 32 + lane]);
                float2 v1 = __half22float2(g_s[s1 * 32 + lane]);
                float2 v2 = __half22float2(g_s[s2 * 32 + lane]);
                float2 v3 = __half22float2(g_s[s3 * 32 + lane]);
                float d0 = rsqrtf((float)(g_cnt[s0] + 1));
                float d1 = rsqrtf((float)(g_cnt[s1] + 1));
                float d2 = rsqrtf((float)(g_cnt[s2] + 1));
                float d3 = rsqrtf((float)(g_cnt[s3] + 1));
                acc.x = fmaf(d0, v0.x, acc.x); acc.y = fmaf(d0, v0.y, acc.y);
                acc.x = fmaf(d1, v1.x, acc.x); acc.y = fmaf(d1, v1.y, acc.y);
                acc.x = fmaf(d2, v2.x, acc.x); acc.y = fmaf(d2, v2.y, acc.y);
                acc.x = fmaf(d3, v3.x, acc.x); acc.y = fmaf(d3, v3.y, acc.y);
            }
            for (; e < deg; ++e) {
                int s0 = row[e];
                float2 v = __half22float2(g_s[s0 * 32 + lane]);
                float d0 = rsqrtf((float)(g_cnt[s0] + 1));
                acc.x = fmaf(d0, v.x, acc.x); acc.y = fmaf(d0, v.y, acc.y);
            }

            float ox = fmaxf(fmaf(di, acc.x, b.x), 0.0f);
            float oy = fmaxf(fmaf(di, acc.y, b.y), 0.0f);
            int r = i - row0;
            Xt[(2 * lane)     * 68 + r] = ox;   // h transposed, ready for gemm
            Xt[(2 * lane + 1) * 68 + r] = oy;
        }
    }
    __syncthreads();

    // phase 2: gemm from smem (h never touched gmem)
    gemm_tile_from_smem<1>(Ws, Xt, row0, n, tid, g_s2);
}

// ---------------- Kernel C: agg2 + counter reset ----------------------------
// out = dinv_i*(s2_i + sum s2_src) + b2;  then g_cnt[i] = 0 for next replay
__global__ __launch_bounds__(256) void agg2_kernel(
    const float* __restrict__ b2, float* __restrict__ out, int n)
{
    int i = (blockIdx.x * blockDim.x + threadIdx.x) >> 5;
    int lane = threadIdx.x & 31;
    if (i >= n) return;

    int cnt = g_cnt[i];
    int deg = min(cnt, CAP);
    float di = rsqrtf((float)(cnt + 1));
    if (lane == 0) g_cnt[i] = 0;     // reset for next replay (sole reader is this warp)

    float2 acc = __half22float2(g_s2[i * 32 + lane]);

    const int* __restrict__ row = &g_col2[i * CAP];
    int e = 0;
    for (; e + 4 <= deg; e += 4) {
        int s0 = row[e], s1 = row[e + 1], s2 = row[e + 2], s3 = row[e + 3];
        float2 v0 = __half22float2(g_s2[s0 * 32 + lane]);
        float2 v1 = __half22float2(g_s2[s1 * 32 + lane]);
        float2 v2 = __half22float2(g_s2[s2 * 32 + lane]);
        float2 v3 = __half22float2(g_s2[s3 * 32 + lane]);
        acc.x += (v0.x + v1.x) + (v2.x + v3.x);
        acc.y += (v0.y + v1.y) + (v2.y + v3.y);
    }
    for (; e < deg; ++e) {
        int s0 = row[e];
        float2 v = __half22float2(g_s2[s0 * 32 + lane]);
        acc.x += v.x; acc.y += v.y;
    }

    float2 b = ((const float2*)b2)[lane];
    float ox = fmaf(di, acc.x, b.x);
    float oy = fmaf(di, acc.y, b.y);
    ((float2*)out)[i * 32 + lane] = make_float2(ox, oy);
}

// ---------------- launch -----------------------------------------------------
extern "C" void kernel_launch(void* const* d_in, const int* in_sizes, int n_in,
                              void* d_out, int out_size) {
    const float* x  = (const float*)d_in[0];
    const int*   ei = (const int*)d_in[1];    // int32 (JAX x64 disabled)
    const float* W1 = (const float*)d_in[2];
    const float* b1 = (const float*)d_in[3];
    const float* W2 = (const float*)d_in[4];
    const float* b2 = (const float*)d_in[5];
    float* out = (float*)d_out;

    int N = in_sizes[0] / DFEAT;
    int E = in_sizes[1] / 2;

    int gemm_blocks = (N + 63) / 64;
    int fill_blocks = (E + 2047) / 2048;
    int agg_blocks  = (N * 32 + 255) / 256;

    build_gemm1_kernel<<<gemm_blocks + fill_blocks, 256>>>(x, W1, ei, N, E, gemm_blocks);
    agg1_gemm2_kernel<<<gemm_blocks, 256>>>(b1, W2, N);
    agg2_kernel<<<agg_blocks, 256>>>(b2, out, N);
}

// round 11
// speedup vs baseline: 2.1258x; 2.1258x over previous
#include <cuda_runtime.h>
#include <cuda_fp16.h>

#define DFEAT 64
#define MAXN 50048
#define MAXE 1600000
#define CAP 128   // bucket capacity; in-deg Poisson(32), 128 ~ 17 sigma

// ---------------- scratch (device globals; no allocation allowed) -----------
__device__ int     g_cnt[MAXN];            // in-degree counters (memset per launch)
__device__ int     g_col2[MAXN * CAP];     // bucketed adjacency
__device__ __half2 g_s[MAXN * 32];         // fp16 feature buffer (s1, then s2)
__device__ float   g_h[MAXN * DFEAT];      // layer-1 activations (fp32)

// ---------------- direct bucket fill -----------------------------------------
__global__ void fill_direct_kernel(const int* __restrict__ ei, int E, int n) {
    int e = blockIdx.x * blockDim.x + threadIdx.x;
    if (e < E) {
        int src = ei[e];
        int dst = ei[E + e];
        if ((unsigned)dst < (unsigned)n && (unsigned)src < (unsigned)n) {
            int pos = atomicAdd(&g_cnt[dst], 1);
            if (pos < CAP) g_col2[dst * CAP + pos] = src;
        }
    }
}

// ---------------- in-place pre-scale: s1[i] *= dinv(i) ----------------------
// one thread per half2 element; cnt load is broadcast within each node's warp
__global__ __launch_bounds__(256) void scale_s1_kernel(int n) {
    int idx = blockIdx.x * blockDim.x + threadIdx.x;
    if (idx < n * 32) {
        int node = idx >> 5;
        float di = rsqrtf((float)(g_cnt[node] + 1));
        float2 v = __half22float2(g_s[idx]);
        g_s[idx] = __floats2half2_rn(di * v.x, di * v.y);
    }
}

// ---------------- GEMM: s = [dinv ⊙] (X @ W), fp16 out, FFMA2 mainloop ------
template<int SCALE, int USE_H>
__global__ __launch_bounds__(256) void gemm_kernel(
    const float* __restrict__ Xext, const float* __restrict__ W, int n)
{
    __shared__ float Ws[DFEAT * 68];   // Ws[k*68 + c]
    __shared__ float Xt[DFEAT * 68];   // Xt[k*68 + r]  (transposed)

    const float* __restrict__ X = USE_H ? g_h : Xext;
    const float4* __restrict__ W4 = (const float4*)W;
    const float4* __restrict__ X4 = (const float4*)X;

    int tid = threadIdx.x;
    int row0 = blockIdx.x * 64;

    for (int i = tid; i < 64 * 16; i += 256) {
        int r = i >> 4, c4 = i & 15;
        *(float4*)&Ws[r * 68 + c4 * 4] = W4[i];
        int gr = row0 + r;
        float4 xv = (gr < n) ? X4[gr * 16 + c4] : make_float4(0.f, 0.f, 0.f, 0.f);
        int k0 = c4 * 4;
        Xt[(k0 + 0) * 68 + r] = xv.x;
        Xt[(k0 + 1) * 68 + r] = xv.y;
        Xt[(k0 + 2) * 68 + r] = xv.z;
        Xt[(k0 + 3) * 68 + r] = xv.w;
    }
    __syncthreads();

    int tx = tid & 15;      // cols tx*4 .. tx*4+3
    int ty = tid >> 4;      // rows ty*4 .. ty*4+3
    unsigned long long accA[4] = {0ull, 0ull, 0ull, 0ull};
    unsigned long long accB[4] = {0ull, 0ull, 0ull, 0ull};

#pragma unroll 8
    for (int k = 0; k < DFEAT; k++) {
        float4 xv = *(const float4*)&Xt[k * 68 + ty * 4];
        ulonglong2 wv = *(const ulonglong2*)&Ws[k * 68 + tx * 4];
        float xr[4] = {xv.x, xv.y, xv.z, xv.w};
#pragma unroll
        for (int r = 0; r < 4; r++) {
            unsigned int xu = __float_as_uint(xr[r]);
            unsigned long long ax;
            asm("mov.b64 %0, {%1,%1};" : "=l"(ax) : "r"(xu));
            asm("fma.rn.f32x2 %0, %1, %2, %0;" : "+l"(accA[r]) : "l"(ax), "l"(wv.x));
            asm("fma.rn.f32x2 %0, %1, %2, %0;" : "+l"(accB[r]) : "l"(ax), "l"(wv.y));
        }
    }

#pragma unroll
    for (int r = 0; r < 4; r++) {
        int gr = row0 + ty * 4 + r;
        if (gr < n) {
            unsigned int u0, u1, u2, u3;
            asm("mov.b64 {%0,%1}, %2;" : "=r"(u0), "=r"(u1) : "l"(accA[r]));
            asm("mov.b64 {%0,%1}, %2;" : "=r"(u2), "=r"(u3) : "l"(accB[r]));
            float o0 = __uint_as_float(u0), o1 = __uint_as_float(u1);
            float o2 = __uint_as_float(u2), o3 = __uint_as_float(u3);
            if (SCALE) {
                float di = rsqrtf((float)(g_cnt[gr] + 1));
                o0 *= di; o1 *= di; o2 *= di; o3 *= di;
            }
            __half2 h0 = __floats2half2_rn(o0, o1);
            __half2 h1 = __floats2half2_rn(o2, o3);
            uint2 pk;
            pk.x = *(unsigned int*)&h0;
            pk.y = *(unsigned int*)&h1;
            *(uint2*)&g_s[gr * 32 + tx * 2] = pk;
        }
    }
}

// ---------------- aggregation: warp per node, s pre-scaled ------------------
// out = (relu?) dinv_i * (s[i] + sum s[src]) + b   (one 128B gather per edge)
template<int RELU, int EXTOUT>
__global__ __launch_bounds__(256) void agg_kernel(
    const float* __restrict__ bias, float* __restrict__ outext, int n)
{
    int i = (blockIdx.x * blockDim.x + threadIdx.x) >> 5;
    int lane = threadIdx.x & 31;
    if (i >= n) return;

    const __half2* __restrict__ Sv = g_s;
    int cnt = g_cnt[i];
    int deg = min(cnt, CAP);
    float di = rsqrtf((float)(cnt + 1));

    float2 acc = __half22float2(Sv[i * 32 + lane]);   // self (pre-scaled)

    const int* __restrict__ row = &g_col2[i * CAP];
    int e = 0;
    for (; e + 8 <= deg; e += 8) {
        int s0 = row[e],     s1 = row[e + 1], s2 = row[e + 2], s3 = row[e + 3];
        int s4 = row[e + 4], s5 = row[e + 5], s6 = row[e + 6], s7 = row[e + 7];
        float2 v0 = __half22float2(Sv[s0 * 32 + lane]);
        float2 v1 = __half22float2(Sv[s1 * 32 + lane]);
        float2 v2 = __half22float2(Sv[s2 * 32 + lane]);
        float2 v3 = __half22float2(Sv[s3 * 32 + lane]);
        float2 v4 = __half22float2(Sv[s4 * 32 + lane]);
        float2 v5 = __half22float2(Sv[s5 * 32 + lane]);
        float2 v6 = __half22float2(Sv[s6 * 32 + lane]);
        float2 v7 = __half22float2(Sv[s7 * 32 + lane]);
        acc.x += ((v0.x + v1.x) + (v2.x + v3.x)) + ((v4.x + v5.x) + (v6.x + v7.x));
        acc.y += ((v0.y + v1.y) + (v2.y + v3.y)) + ((v4.y + v5.y) + (v6.y + v7.y));
    }
    for (; e + 4 <= deg; e += 4) {
        int s0 = row[e], s1 = row[e + 1], s2 = row[e + 2], s3 = row[e + 3];
        float2 v0 = __half22float2(Sv[s0 * 32 + lane]);
        float2 v1 = __half22float2(Sv[s1 * 32 + lane]);
        float2 v2 = __half22float2(Sv[s2 * 32 + lane]);
        float2 v3 = __half22float2(Sv[s3 * 32 + lane]);
        acc.x += (v0.x + v1.x) + (v2.x + v3.x);
        acc.y += (v0.y + v1.y) + (v2.y + v3.y);
    }
    for (; e < deg; ++e) {
        int s0 = row[e];
        float2 v = __half22float2(Sv[s0 * 32 + lane]);
        acc.x += v.x; acc.y += v.y;
    }

    float2 b = ((const float2*)bias)[lane];
    float ox = fmaf(di, acc.x, b.x);
    float oy = fmaf(di, acc.y, b.y);
    if (RELU) { ox = fmaxf(ox, 0.0f); oy = fmaxf(oy, 0.0f); }

    float2* __restrict__ O = EXTOUT ? (float2*)outext : (float2*)g_h;
    O[i * 32 + lane] = make_float2(ox, oy);
}

// ---------------- launch -----------------------------------------------------
static cudaStream_t g_s2str;
static cudaEvent_t  g_evFork, g_evJoin;
static int*         g_cnt_addr = nullptr;
static bool         g_init = false;

extern "C" void kernel_launch(void* const* d_in, const int* in_sizes, int n_in,
                              void* d_out, int out_size) {
    const float* x  = (const float*)d_in[0];
    const int*   ei = (const int*)d_in[1];    // int32 (JAX x64 disabled)
    const float* W1 = (const float*)d_in[2];
    const float* b1 = (const float*)d_in[3];
    const float* W2 = (const float*)d_in[4];
    const float* b2 = (const float*)d_in[5];
    float* out = (float*)d_out;

    int N = in_sizes[0] / DFEAT;
    int E = in_sizes[1] / 2;

    if (!g_init) {  // one-time handle creation (correctness call precedes capture)
        cudaStreamCreateWithFlags(&g_s2str, cudaStreamNonBlocking);
        cudaEventCreateWithFlags(&g_evFork, cudaEventDisableTiming);
        cudaEventCreateWithFlags(&g_evJoin, cudaEventDisableTiming);
        cudaGetSymbolAddress((void**)&g_cnt_addr, g_cnt);
        g_init = true;
    }

    int gemm_blocks  = (N + 63) / 64;
    int agg_blocks   = (N * 32 + 255) / 256;
    int scale_blocks = (N * 32 + 255) / 256;

    // fork: gemm1 (unscaled, graph-independent) on side stream
    cudaEventRecord(g_evFork, 0);
    cudaStreamWaitEvent(g_s2str, g_evFork, 0);
    gemm_kernel<0, 0><<<gemm_blocks, 256, 0, g_s2str>>>(x, W1, N);
    cudaEventRecord(g_evJoin, g_s2str);

    // main stream: bucket adjacency build
    cudaMemsetAsync(g_cnt_addr, 0, N * sizeof(int), 0);
    fill_direct_kernel<<<(E + 255) / 256, 256>>>(ei, E, N);

    // join, then pre-scale s1 by dinv (removes per-edge dinv gathers in agg1)
    cudaStreamWaitEvent(0, g_evJoin, 0);
    scale_s1_kernel<<<scale_blocks, 256>>>(N);

    // layer 1: h = relu(dinv*(s1[i] + sum s1[src]) + b1)
    agg_kernel<1, 0><<<agg_blocks, 256>>>(b1, out, N);
    // layer 2: s2 = dinv ⊙ (h @ W2); out = dinv*(s2[i] + sum s2[src]) + b2
    gemm_kernel<1, 1><<<gemm_blocks, 256>>>(x, W2, N);
    agg_kernel<0, 1><<<agg_blocks, 256>>>(b2, out, N);
}

// round 13
// speedup vs baseline: 2.2967x; 1.0804x over previous
#include <cuda_runtime.h>
#include <cuda_fp16.h>

#define DFEAT 64
#define MAXN 50048
#define MAXE 1600000
#define CAP 128   // bucket capacity; in-deg Poisson(32), 128 ~ 17 sigma

// ---------------- scratch (device globals; no allocation allowed) -----------
__device__ int     g_cnt[MAXN];            // in-degree counters (memset per launch)
__device__ int     g_col2[MAXN * CAP];     // bucketed adjacency
__device__ __half2 g_s[MAXN * 32];         // fp16 feature buffer (s1, then s2)
__device__ float   g_h[MAXN * DFEAT];      // layer-1 activations (fp32)

// ---------------- direct bucket fill -----------------------------------------
__global__ void fill_direct_kernel(const int* __restrict__ ei, int E, int n) {
    int e = blockIdx.x * blockDim.x + threadIdx.x;
    if (e < E) {
        int src = ei[e];
        int dst = ei[E + e];
        if ((unsigned)dst < (unsigned)n && (unsigned)src < (unsigned)n) {
            int pos = atomicAdd(&g_cnt[dst], 1);
            if (pos < CAP) g_col2[dst * CAP + pos] = src;
        }
    }
}

// ---------------- in-place pre-scale: s1[i] *= dinv(i) ----------------------
__global__ __launch_bounds__(256) void scale_s1_kernel(int n) {
    int idx = blockIdx.x * blockDim.x + threadIdx.x;
    if (idx < n * 32) {
        int node = idx >> 5;
        float di = rsqrtf((float)(g_cnt[node] + 1));
        float2 v = __half22float2(g_s[idx]);
        g_s[idx] = __floats2half2_rn(di * v.x, di * v.y);
    }
}

// ---------------- GEMM: s = [dinv ⊙] (X @ W), fp16 out, FFMA2 mainloop ------
template<int SCALE, int USE_H>
__global__ __launch_bounds__(256) void gemm_kernel(
    const float* __restrict__ Xext, const float* __restrict__ W, int n)
{
    __shared__ float Ws[DFEAT * 68];   // Ws[k*68 + c]
    __shared__ float Xt[DFEAT * 68];   // Xt[k*68 + r]  (transposed)

    const float* __restrict__ X = USE_H ? g_h : Xext;
    const float4* __restrict__ W4 = (const float4*)W;
    const float4* __restrict__ X4 = (const float4*)X;

    int tid = threadIdx.x;
    int row0 = blockIdx.x * 64;

    for (int i = tid; i < 64 * 16; i += 256) {
        int r = i >> 4, c4 = i & 15;
        *(float4*)&Ws[r * 68 + c4 * 4] = W4[i];
        int gr = row0 + r;
        float4 xv = (gr < n) ? X4[gr * 16 + c4] : make_float4(0.f, 0.f, 0.f, 0.f);
        int k0 = c4 * 4;
        Xt[(k0 + 0) * 68 + r] = xv.x;
        Xt[(k0 + 1) * 68 + r] = xv.y;
        Xt[(k0 + 2) * 68 + r] = xv.z;
        Xt[(k0 + 3) * 68 + r] = xv.w;
    }
    __syncthreads();

    int tx = tid & 15;      // cols tx*4 .. tx*4+3
    int ty = tid >> 4;      // rows ty*4 .. ty*4+3
    unsigned long long accA[4] = {0ull, 0ull, 0ull, 0ull};
    unsigned long long accB[4] = {0ull, 0ull, 0ull, 0ull};

#pragma unroll 8
    for (int k = 0; k < DFEAT; k++) {
        float4 xv = *(const float4*)&Xt[k * 68 + ty * 4];
        ulonglong2 wv = *(const ulonglong2*)&Ws[k * 68 + tx * 4];
        float xr[4] = {xv.x, xv.y, xv.z, xv.w};
#pragma unroll
        for (int r = 0; r < 4; r++) {
            unsigned int xu = __float_as_uint(xr[r]);
            unsigned long long ax;
            asm("mov.b64 %0, {%1,%1};" : "=l"(ax) : "r"(xu));
            asm("fma.rn.f32x2 %0, %1, %2, %0;" : "+l"(accA[r]) : "l"(ax), "l"(wv.x));
            asm("fma.rn.f32x2 %0, %1, %2, %0;" : "+l"(accB[r]) : "l"(ax), "l"(wv.y));
        }
    }

#pragma unroll
    for (int r = 0; r < 4; r++) {
        int gr = row0 + ty * 4 + r;
        if (gr < n) {
            unsigned int u0, u1, u2, u3;
            asm("mov.b64 {%0,%1}, %2;" : "=r"(u0), "=r"(u1) : "l"(accA[r]));
            asm("mov.b64 {%0,%1}, %2;" : "=r"(u2), "=r"(u3) : "l"(accB[r]));
            float o0 = __uint_as_float(u0), o1 = __uint_as_float(u1);
            float o2 = __uint_as_float(u2), o3 = __uint_as_float(u3);
            if (SCALE) {
                float di = rsqrtf((float)(g_cnt[gr] + 1));
                o0 *= di; o1 *= di; o2 *= di; o3 *= di;
            }
            __half2 h0 = __floats2half2_rn(o0, o1);
            __half2 h1 = __floats2half2_rn(o2, o3);
            uint2 pk;
            pk.x = *(unsigned int*)&h0;
            pk.y = *(unsigned int*)&h1;
            *(uint2*)&g_s[gr * 32 + tx * 2] = pk;
        }
    }
}

// ---------------- aggregation: warp per node, s pre-scaled ------------------
// out = (relu?) dinv_i * (s[i] + sum s[src]) + b
// indices via LDG.128; 4-edge fp16 pairwise trees feed an fp32 accumulator.
template<int RELU, int EXTOUT>
__global__ __launch_bounds__(256) void agg_kernel(
    const float* __restrict__ bias, float* __restrict__ outext, int n)
{
    int i = (blockIdx.x * blockDim.x + threadIdx.x) >> 5;
    int lane = threadIdx.x & 31;
    if (i >= n) return;

    const __half2* __restrict__ Sv = g_s;
    int cnt = g_cnt[i];
    int deg = min(cnt, CAP);
    float di = rsqrtf((float)(cnt + 1));

    float2 acc = __half22float2(Sv[i * 32 + lane]);   // self (pre-scaled)

    const int4* __restrict__ row4 = (const int4*)&g_col2[i * CAP];  // 512B-aligned
    int e = 0;
    for (; e + 8 <= deg; e += 8) {
        int4 ia = row4[e >> 2];
        int4 ib = row4[(e >> 2) + 1];
        __half2 v0 = Sv[ia.x * 32 + lane];
        __half2 v1 = Sv[ia.y * 32 + lane];
        __half2 v2 = Sv[ia.z * 32 + lane];
        __half2 v3 = Sv[ia.w * 32 + lane];
        __half2 v4 = Sv[ib.x * 32 + lane];
        __half2 v5 = Sv[ib.y * 32 + lane];
        __half2 v6 = Sv[ib.z * 32 + lane];
        __half2 v7 = Sv[ib.w * 32 + lane];
        __half2 q0 = __hadd2(__hadd2(v0, v1), __hadd2(v2, v3));
        __half2 q1 = __hadd2(__hadd2(v4, v5), __hadd2(v6, v7));
        float2 f0 = __half22float2(q0);
        float2 f1 = __half22float2(q1);
        acc.x += f0.x + f1.x;
        acc.y += f0.y + f1.y;
    }
    if (e + 4 <= deg) {
        int4 ia = row4[e >> 2];
        __half2 v0 = Sv[ia.x * 32 + lane];
        __half2 v1 = Sv[ia.y * 32 + lane];
        __half2 v2 = Sv[ia.z * 32 + lane];
        __half2 v3 = Sv[ia.w * 32 + lane];
        __half2 q0 = __hadd2(__hadd2(v0, v1), __hadd2(v2, v3));
        float2 f0 = __half22float2(q0);
        acc.x += f0.x;
        acc.y += f0.y;
        e += 4;
    }
    const int* __restrict__ row = &g_col2[i * CAP];
    for (; e < deg; ++e) {
        float2 v = __half22float2(Sv[row[e] * 32 + lane]);
        acc.x += v.x; acc.y += v.y;
    }

    float2 b = ((const float2*)bias)[lane];
    float ox = fmaf(di, acc.x, b.x);
    float oy = fmaf(di, acc.y, b.y);
    if (RELU) { ox = fmaxf(ox, 0.0f); oy = fmaxf(oy, 0.0f); }

    float2* __restrict__ O = EXTOUT ? (float2*)outext : (float2*)g_h;
    O[i * 32 + lane] = make_float2(ox, oy);
}

// ---------------- launch -----------------------------------------------------
static cudaStream_t g_s2str;
static cudaEvent_t  g_evFork, g_evJoin;
static int*         g_cnt_addr = nullptr;
static bool         g_init = false;

extern "C" void kernel_launch(void* const* d_in, const int* in_sizes, int n_in,
                              void* d_out, int out_size) {
    const float* x  = (const float*)d_in[0];
    const int*   ei = (const int*)d_in[1];    // int32 (JAX x64 disabled)
    const float* W1 = (const float*)d_in[2];
    const float* b1 = (const float*)d_in[3];
    const float* W2 = (const float*)d_in[4];
    const float* b2 = (const float*)d_in[5];
    float* out = (float*)d_out;

    int N = in_sizes[0] / DFEAT;
    int E = in_sizes[1] / 2;

    if (!g_init) {  // one-time handle creation (correctness call precedes capture)
        cudaStreamCreateWithFlags(&g_s2str, cudaStreamNonBlocking);
        cudaEventCreateWithFlags(&g_evFork, cudaEventDisableTiming);
        cudaEventCreateWithFlags(&g_evJoin, cudaEventDisableTiming);
        cudaGetSymbolAddress((void**)&g_cnt_addr, g_cnt);
        g_init = true;
    }

    int gemm_blocks  = (N + 63) / 64;
    int agg_blocks   = (N * 32 + 255) / 256;
    int scale_blocks = (N * 32 + 255) / 256;

    // fork: gemm1 (unscaled, graph-independent) on side stream
    cudaEventRecord(g_evFork, 0);
    cudaStreamWaitEvent(g_s2str, g_evFork, 0);
    gemm_kernel<0, 0><<<gemm_blocks, 256, 0, g_s2str>>>(x, W1, N);
    cudaEventRecord(g_evJoin, g_s2str);

    // main stream: bucket adjacency build
    cudaMemsetAsync(g_cnt_addr, 0, N * sizeof(int), 0);
    fill_direct_kernel<<<(E + 255) / 256, 256>>>(ei, E, N);

    // join, then pre-scale s1 by dinv
    cudaStreamWaitEvent(0, g_evJoin, 0);
    scale_s1_kernel<<<scale_blocks, 256>>>(N);

    // layer 1: h = relu(dinv*(s1[i] + sum s1[src]) + b1)
    agg_kernel<1, 0><<<agg_blocks, 256>>>(b1, out, N);
    // layer 2: s2 = dinv ⊙ (h @ W2); out = dinv*(s2[i] + sum s2[src]) + b2
    gemm_kernel<1, 1><<<gemm_blocks, 256>>>(x, W2, N);
    agg_kernel<0, 1><<<agg_blocks, 256>>>(b2, out, N);
}